// round 13
// baseline (speedup 1.0000x reference)
#include <cuda_runtime.h>
#include <cuda_bf16.h>
#include <cstdint>

#define BATCH 4
#define CH    128
#define HW    4096
#define RB    64          // row-blocks of 64 rows

typedef __nv_bfloat16 bf16;

// ---------------- scratch (static device memory) ----------------------------
__device__ bf16  g_Qhi[BATCH * HW * CH];           // [b][i][c]
__device__ bf16  g_Qlo[BATCH * HW * CH];
__device__ bf16  g_Khi[BATCH * HW * CH];           // [b][j][c]
__device__ bf16  g_Klo[BATCH * HW * CH];
__device__ float g_V  [BATCH * CH * HW];           // [b][c][j]
__device__ bf16  g_Vp [BATCH * CH * HW];           // V/colsum, single bf16
__device__ bf16  g_E  [(size_t)BATCH * HW * HW];   // exp(scores), single bf16
__device__ float g_colpart[BATCH * RB * HW];

// ---------------- helpers ----------------------------------------------------
__device__ __forceinline__ uint32_t smem_u32(const void* p) {
    uint32_t a;
    asm("{ .reg .u64 t; cvta.to.shared.u64 t, %1; cvt.u32.u64 %0, t; }" : "=r"(a) : "l"(p));
    return a;
}
__device__ __forceinline__ uint32_t lds32(uint32_t a) {
    uint32_t v;
    asm volatile("ld.shared.b32 %0, [%1];" : "=r"(v) : "r"(a));
    return v;
}
__device__ __forceinline__ void cp16(uint32_t dst, const void* src) {
    asm volatile("cp.async.cg.shared.global [%0], [%1], 16;" :: "r"(dst), "l"(src) : "memory");
}
__device__ __forceinline__ void cp_commit() {
    asm volatile("cp.async.commit_group;" ::: "memory");
}
template<int N> __device__ __forceinline__ void cp_wait() {
    asm volatile("cp.async.wait_group %0;" :: "n"(N) : "memory");
}
// D += A(row,m16k16 bf16) * B(col,k16n8 bf16), fp32 accum
__device__ __forceinline__ void mma_bf16(float* c, const uint32_t* a, const uint32_t* b) {
    asm volatile(
        "mma.sync.aligned.m16n8k16.row.col.f32.bf16.bf16.f32 "
        "{%0,%1,%2,%3}, {%4,%5,%6,%7}, {%8,%9}, {%0,%1,%2,%3};"
        : "+f"(c[0]), "+f"(c[1]), "+f"(c[2]), "+f"(c[3])
        : "r"(a[0]), "r"(a[1]), "r"(a[2]), "r"(a[3]), "r"(b[0]), "r"(b[1]));
}
__device__ __forceinline__ void split_bf16(float v, bf16& h, bf16& l) {
    h = __float2bfloat16(v);
    l = __float2bfloat16(v - __bfloat162float(h));
}

// ---------------------------------------------------------------------------
// Kernel 1: QKV projection (unchanged — measured at its fp32 FFMA floor).
// ---------------------------------------------------------------------------
__global__ void proj_kernel(const float* __restrict__ X,
                            const float* __restrict__ Wq, const float* __restrict__ bq,
                            const float* __restrict__ Wk, const float* __restrict__ bk,
                            const float* __restrict__ Wv, const float* __restrict__ bv)
{
    const int p  = blockIdx.y;
    const float* W    = (p == 0) ? Wq : (p == 1) ? Wk : Wv;
    const float* bias = (p == 0) ? bq : (p == 1) ? bk : bv;

    const int b  = blockIdx.z;
    const int i0 = blockIdx.x * 32;
    const int o  = threadIdx.x;

    __shared__ float Xs[CH][32];
    __shared__ float T[32][132];

    for (int idx = threadIdx.x; idx < CH * 32; idx += 128) {
        int c  = idx >> 5;
        int ii = idx & 31;
        Xs[c][ii] = X[((size_t)b * CH + c) * HW + i0 + ii];
    }
    __syncthreads();

    float acc[32];
#pragma unroll
    for (int ii = 0; ii < 32; ii++) acc[ii] = 0.f;
    for (int c = 0; c < CH; c += 4) {
        float4 w4 = *reinterpret_cast<const float4*>(&W[o * CH + c]);
        float w[4] = {w4.x, w4.y, w4.z, w4.w};
#pragma unroll
        for (int cc = 0; cc < 4; cc++)
#pragma unroll
            for (int ii = 0; ii < 32; ii++)
                acc[ii] += w[cc] * Xs[c + cc][ii];
    }
    const float bo = bias[o];

    if (p == 2) {
        float* op = &g_V[((size_t)b * CH + o) * HW + i0];
#pragma unroll
        for (int ii = 0; ii < 32; ii++) op[ii] = acc[ii] + bo;
    } else {
#pragma unroll
        for (int ii = 0; ii < 32; ii++) T[ii][o] = acc[ii] + bo;
        __syncthreads();
        bf16* hi = (p == 0) ? g_Qhi : g_Khi;
        bf16* lo = (p == 0) ? g_Qlo : g_Klo;
#pragma unroll
        for (int k = 0; k < 16; k++) {
            int gi  = threadIdx.x + k * 128;
            int row = gi >> 6;
            int cp  = (gi & 63) * 2;
            float v0 = T[row][cp];
            float v1 = T[row][cp + 1];
            bf16 h0, l0, h1, l1;
            split_bf16(v0, h0, l0);
            split_bf16(v1, h1, l1);
            size_t base = ((size_t)b * HW + i0 + row) * CH + cp;
            *reinterpret_cast<__nv_bfloat162*>(&hi[base]) = __nv_bfloat162(h0, h1);
            *reinterpret_cast<__nv_bfloat162*>(&lo[base]) = __nv_bfloat162(l0, l1);
        }
    }
}

// ---------------------------------------------------------------------------
// Kernel 2: scores.  E = exp(Q K^T) (3-pass split), single bf16 store + colsums.
// CTA 64(i) x 64(j).  warps 2(wm: 32 rows) x 4(wn: 16 cols).
// k in 4 chunks of 32.  2-stage, one sync/chunk.  4 CTAs/SM (32 warps).
// smem: 2 x (256 rows x 80B) = 40960 -> 4 CTAs/SM.
// ---------------------------------------------------------------------------
#define SC_TROW  80
#define SC_T     5120     // 64*80 per tile
#define SC_STAGE 20480    // Qhi,Qlo,Khi,Klo
#define SC_SMEM  40960    // 2 stages

__global__ void __launch_bounds__(256, 4) scores_kernel()
{
    extern __shared__ char smem[];
    const uint32_t sb = smem_u32(smem);
    const int tid = threadIdx.x, wid = tid >> 5, lane = tid & 31;
    const int g = lane >> 2, t = lane & 3;
    const int wm = wid & 1, wn = wid >> 1;   // 2 m-halves(32) x 4 n-strips(16)
    const int b = blockIdx.z, i0 = blockIdx.y * 64, j0 = blockIdx.x * 64;

    const bf16* bases[4] = {
        g_Qhi + ((size_t)b * HW + i0) * CH,
        g_Qlo + ((size_t)b * HW + i0) * CH,
        g_Khi + ((size_t)b * HW + j0) * CH,
        g_Klo + ((size_t)b * HW + j0) * CH };

    float acc[2][2][4];
#pragma unroll
    for (int a = 0; a < 2; a++)
#pragma unroll
        for (int n = 0; n < 2; n++)
#pragma unroll
            for (int r = 0; r < 4; r++) acc[a][n][r] = 0.f;

    // 4 tiles x 64 rows x 4 segs of 16B = 1024 ops = 4/thread
    auto issue = [&](int st, int kc) {
        uint32_t sd = sb + st * SC_STAGE;
#pragma unroll
        for (int w = 0; w < 4; w++) {
            int idx  = w * 256 + tid;
            int tile = idx >> 8;
            int row  = (idx >> 2) & 63;
            int seg  = idx & 3;
            cp16(sd + tile * SC_T + row * SC_TROW + seg * 16,
                 bases[tile] + (size_t)row * CH + kc * 32 + seg * 8);
        }
    };

    issue(0, 0); cp_commit();
    for (int kc = 0; kc < 4; kc++) {
        if (kc < 3) { issue((kc + 1) & 1, kc + 1); cp_commit(); cp_wait<1>(); }
        else        { cp_wait<0>(); }
        __syncthreads();

        const uint32_t SB  = sb + (kc & 1) * SC_STAGE;
        const uint32_t TAh = SB, TAl = SB + SC_T;
        const uint32_t TBh = SB + 2 * SC_T, TBl = SB + 3 * SC_T;
        const uint32_t rowA = (wm * 32 + g) * SC_TROW;
        const uint32_t rowB = (wn * 16 + g) * SC_TROW;
#pragma unroll
        for (int ks = 0; ks < 2; ks++) {
            const uint32_t wo0 = ks * 32 + t * 4, wo1 = wo0 + 16;
            uint32_t ah[2][4], al[2][4], bh[2][2], bl[2][2];
            // staggered loads to limit live registers: hh -> hl -> lh
#pragma unroll
            for (int mt = 0; mt < 2; mt++) {
                uint32_t o = rowA + mt * (16 * SC_TROW);
                ah[mt][0] = lds32(TAh + o + wo0);
                ah[mt][1] = lds32(TAh + o + 8 * SC_TROW + wo0);
                ah[mt][2] = lds32(TAh + o + wo1);
                ah[mt][3] = lds32(TAh + o + 8 * SC_TROW + wo1);
            }
#pragma unroll
            for (int nt = 0; nt < 2; nt++) {
                uint32_t o = rowB + nt * (8 * SC_TROW);
                bh[nt][0] = lds32(TBh + o + wo0);
                bh[nt][1] = lds32(TBh + o + wo1);
            }
#pragma unroll
            for (int mt = 0; mt < 2; mt++)
#pragma unroll
                for (int nt = 0; nt < 2; nt++)
                    mma_bf16(acc[mt][nt], ah[mt], bh[nt]);   // hi*hi
#pragma unroll
            for (int nt = 0; nt < 2; nt++) {
                uint32_t o = rowB + nt * (8 * SC_TROW);
                bl[nt][0] = lds32(TBl + o + wo0);
                bl[nt][1] = lds32(TBl + o + wo1);
            }
#pragma unroll
            for (int mt = 0; mt < 2; mt++)
#pragma unroll
                for (int nt = 0; nt < 2; nt++)
                    mma_bf16(acc[mt][nt], ah[mt], bl[nt]);   // hi*lo
#pragma unroll
            for (int mt = 0; mt < 2; mt++) {
                uint32_t o = rowA + mt * (16 * SC_TROW);
                al[mt][0] = lds32(TAl + o + wo0);
                al[mt][1] = lds32(TAl + o + 8 * SC_TROW + wo0);
                al[mt][2] = lds32(TAl + o + wo1);
                al[mt][3] = lds32(TAl + o + 8 * SC_TROW + wo1);
            }
#pragma unroll
            for (int mt = 0; mt < 2; mt++)
#pragma unroll
                for (int nt = 0; nt < 2; nt++)
                    mma_bf16(acc[mt][nt], al[mt], bh[nt]);   // lo*hi
        }
        __syncthreads();
    }

    // epilogue: exp, bf16 store (csum over the ROUNDED values), column partials
    float csum[2][2] = {};
    const size_t Eb = (size_t)b * HW * HW;
#pragma unroll
    for (int mt = 0; mt < 2; mt++) {
        const int r0 = i0 + wm * 32 + mt * 16 + g;
#pragma unroll
        for (int nt = 0; nt < 2; nt++) {
            const int jj = j0 + wn * 16 + nt * 8 + 2 * t;
            bf16 h0 = __float2bfloat16(__expf(acc[mt][nt][0]));
            bf16 h1 = __float2bfloat16(__expf(acc[mt][nt][1]));
            bf16 h2 = __float2bfloat16(__expf(acc[mt][nt][2]));
            bf16 h3 = __float2bfloat16(__expf(acc[mt][nt][3]));
            csum[nt][0] += __bfloat162float(h0) + __bfloat162float(h2);
            csum[nt][1] += __bfloat162float(h1) + __bfloat162float(h3);
            size_t o1 = Eb + (size_t)r0 * HW + jj;
            size_t o2 = o1 + (size_t)8 * HW;
            *reinterpret_cast<__nv_bfloat162*>(&g_E[o1]) = __nv_bfloat162(h0, h1);
            *reinterpret_cast<__nv_bfloat162*>(&g_E[o2]) = __nv_bfloat162(h2, h3);
        }
    }
#pragma unroll
    for (int nt = 0; nt < 2; nt++)
#pragma unroll
        for (int p = 0; p < 2; p++) {
            float v = csum[nt][p];
            v += __shfl_xor_sync(0xffffffffu, v, 4);
            v += __shfl_xor_sync(0xffffffffu, v, 8);
            v += __shfl_xor_sync(0xffffffffu, v, 16);
            csum[nt][p] = v;
        }
    float* red = reinterpret_cast<float*>(smem);   // 128 floats, reuse stage smem
    if (lane < 4) {
#pragma unroll
        for (int nt = 0; nt < 2; nt++)
#pragma unroll
            for (int p = 0; p < 2; p++)
                red[wm * 64 + wn * 16 + nt * 8 + 2 * lane + p] = csum[nt][p];
    }
    __syncthreads();
    if (tid < 64)
        g_colpart[((b * RB) + blockIdx.y) * HW + j0 + tid] = red[tid] + red[64 + tid];
}

// ---------------------------------------------------------------------------
// Kernel 3: fused colsum + V normalize (single bf16).
// ---------------------------------------------------------------------------
__global__ void norm_kernel()
{
    int tid = blockIdx.x * blockDim.x + threadIdx.x;   // 0 .. BATCH*HW-1
    int b = tid >> 12;
    int j = tid & (HW - 1);
    float s = 0.f;
#pragma unroll 8
    for (int rb = 0; rb < RB; rb++)
        s += g_colpart[((b * RB) + rb) * HW + j];
    const float inv = 1.0f / s;
    const size_t base = (size_t)b * CH * HW + j;
#pragma unroll 4
    for (int c = 0; c < CH; c++)
        g_Vp[base + (size_t)c * HW] = __float2bfloat16(g_V[base + (size_t)c * HW] * inv);
}

// ---------------------------------------------------------------------------
// Kernel 4: AV, single-pass (unchanged from R12 — proven 115us).
// CTA m=c 128 x n=i 32 -> grid 512.  warps 4(wm) x 2(wn).  k in 64 chunks of 64.
// ---------------------------------------------------------------------------
#define AV_TROW  144
#define AV_VT    18432    // 128*144
#define AV_STAGE 23040    // V(128) + E(32) rows
#define AV_SMEM  46080    // 2 stages

__global__ void __launch_bounds__(256, 4) av_kernel(const float* __restrict__ X,
                                                    float* __restrict__ out)
{
    extern __shared__ char smem[];
    const uint32_t sb = smem_u32(smem);
    const int tid = threadIdx.x, wid = tid >> 5, lane = tid & 31;
    const int g = lane >> 2, t = lane & 3;
    const int wm = wid & 3, wn = wid >> 2;
    const int b = blockIdx.y, i0 = blockIdx.x * 32;

    const bf16* Vp = g_Vp + (size_t)b * CH * HW;
    const bf16* Eb = g_E  + (size_t)b * HW * HW + (size_t)i0 * HW;

    float acc[2][2][4];
#pragma unroll
    for (int a = 0; a < 2; a++)
#pragma unroll
        for (int n = 0; n < 2; n++)
#pragma unroll
            for (int r = 0; r < 4; r++) acc[a][n][r] = 0.f;

    auto issue = [&](int st, int kc) {
        uint32_t sd = sb + st * AV_STAGE;
#pragma unroll
        for (int w = 0; w < 5; w++) {
            int idx = w * 256 + tid;           // 0..1279
            int r   = idx >> 3;
            int seg = idx & 7;
            if (r < 128) {
                cp16(sd + r * AV_TROW + seg * 16,
                     Vp + (size_t)r * HW + kc * 64 + seg * 8);
            } else {
                int row = r - 128;
                cp16(sd + AV_VT + row * AV_TROW + seg * 16,
                     Eb + (size_t)row * HW + kc * 64 + seg * 8);
            }
        }
    };

    issue(0, 0); cp_commit();
    for (int kc = 0; kc < 64; kc++) {
        if (kc < 63) { issue((kc + 1) & 1, kc + 1); cp_commit(); cp_wait<1>(); }
        else         { cp_wait<0>(); }
        __syncthreads();

        const uint32_t TA = sb + (kc & 1) * AV_STAGE;
        const uint32_t TB = TA + AV_VT;
        const uint32_t rowA = (wm * 32 + g) * AV_TROW;
        const uint32_t rowB = (wn * 16 + g) * AV_TROW;
#pragma unroll
        for (int ks = 0; ks < 4; ks++) {
            const uint32_t wo0 = ks * 32 + t * 4, wo1 = wo0 + 16;
            uint32_t ah[2][4], bh[2][2];
#pragma unroll
            for (int mt = 0; mt < 2; mt++) {
                uint32_t o = rowA + mt * (16 * AV_TROW);
                ah[mt][0] = lds32(TA + o + wo0);
                ah[mt][1] = lds32(TA + o + 8 * AV_TROW + wo0);
                ah[mt][2] = lds32(TA + o + wo1);
                ah[mt][3] = lds32(TA + o + 8 * AV_TROW + wo1);
            }
#pragma unroll
            for (int nt = 0; nt < 2; nt++) {
                uint32_t o = rowB + nt * (8 * AV_TROW);
                bh[nt][0] = lds32(TB + o + wo0);
                bh[nt][1] = lds32(TB + o + wo1);
            }
#pragma unroll
            for (int mt = 0; mt < 2; mt++)
#pragma unroll
                for (int nt = 0; nt < 2; nt++)
                    mma_bf16(acc[mt][nt], ah[mt], bh[nt]);
        }
        __syncthreads();
    }

    // epilogue: residual add + coalesced float2 stores
#pragma unroll
    for (int mt = 0; mt < 2; mt++) {
        const int cr = wm * 32 + mt * 16 + g;
#pragma unroll
        for (int nt = 0; nt < 2; nt++) {
            const int ii = i0 + wn * 16 + nt * 8 + 2 * t;
            size_t o1 = ((size_t)b * CH + cr) * HW + ii;
            size_t o2 = o1 + (size_t)8 * HW;   // channel +8
            float2 x1 = *reinterpret_cast<const float2*>(&X[o1]);
            float2 x2 = *reinterpret_cast<const float2*>(&X[o2]);
            float2 r1 = make_float2(x1.x + acc[mt][nt][0], x1.y + acc[mt][nt][1]);
            float2 r2 = make_float2(x2.x + acc[mt][nt][2], x2.y + acc[mt][nt][3]);
            *reinterpret_cast<float2*>(&out[o1]) = r1;
            *reinterpret_cast<float2*>(&out[o2]) = r2;
        }
    }
}

// ---------------------------------------------------------------------------
extern "C" void kernel_launch(void* const* d_in, const int* in_sizes, int n_in,
                              void* d_out, int out_size)
{
    const float* X  = (const float*)d_in[0];
    const float* Wq = (const float*)d_in[1];
    const float* bq = (const float*)d_in[2];
    const float* Wk = (const float*)d_in[3];
    const float* bk = (const float*)d_in[4];
    const float* Wv = (const float*)d_in[5];
    const float* bv = (const float*)d_in[6];
    float* out = (float*)d_out;

    cudaFuncSetAttribute(scores_kernel, cudaFuncAttributeMaxDynamicSharedMemorySize, SC_SMEM);
    cudaFuncSetAttribute(av_kernel,     cudaFuncAttributeMaxDynamicSharedMemorySize, AV_SMEM);

    proj_kernel<<<dim3(HW / 32, 3, BATCH), 128>>>(X, Wq, bq, Wk, bk, Wv, bv);
    scores_kernel<<<dim3(HW / 64, HW / 64, BATCH), 256, SC_SMEM>>>();
    norm_kernel<<<(BATCH * HW) / 256, 256>>>();
    av_kernel<<<dim3(HW / 32, BATCH), 256, AV_SMEM>>>(X, out);
}

// round 17
// speedup vs baseline: 1.1224x; 1.1224x over previous
#include <cuda_runtime.h>
#include <cuda_bf16.h>
#include <cstdint>

#define BATCH 4
#define CH    128
#define HW    4096
#define RB    32          // row-blocks of 128 rows (scores i-tiles)

typedef __nv_bfloat16 bf16;

// ---------------- scratch (static device memory) ----------------------------
__device__ bf16  g_Qhi[BATCH * HW * CH];           // [b][i][c]
__device__ bf16  g_Qlo[BATCH * HW * CH];
__device__ bf16  g_Khi[BATCH * HW * CH];           // [b][j][c]
__device__ bf16  g_Klo[BATCH * HW * CH];
__device__ float g_V  [BATCH * CH * HW];           // [b][c][j]
__device__ bf16  g_Vp [BATCH * CH * HW];           // V/colsum, single bf16
__device__ bf16  g_E  [(size_t)BATCH * HW * HW];   // exp(scores), single bf16
__device__ float g_colpart[BATCH * RB * HW];

// ---------------- helpers ----------------------------------------------------
__device__ __forceinline__ uint32_t smem_u32(const void* p) {
    uint32_t a;
    asm("{ .reg .u64 t; cvta.to.shared.u64 t, %1; cvt.u32.u64 %0, t; }" : "=r"(a) : "l"(p));
    return a;
}
__device__ __forceinline__ uint32_t lds32(uint32_t a) {
    uint32_t v;
    asm volatile("ld.shared.b32 %0, [%1];" : "=r"(v) : "r"(a));
    return v;
}
__device__ __forceinline__ void cp16(uint32_t dst, const void* src) {
    asm volatile("cp.async.cg.shared.global [%0], [%1], 16;" :: "r"(dst), "l"(src) : "memory");
}
__device__ __forceinline__ void cp_commit() {
    asm volatile("cp.async.commit_group;" ::: "memory");
}
template<int N> __device__ __forceinline__ void cp_wait() {
    asm volatile("cp.async.wait_group %0;" :: "n"(N) : "memory");
}
// D += A(row,m16k16 bf16) * B(col,k16n8 bf16), fp32 accum
__device__ __forceinline__ void mma_bf16(float* c, const uint32_t* a, const uint32_t* b) {
    asm volatile(
        "mma.sync.aligned.m16n8k16.row.col.f32.bf16.bf16.f32 "
        "{%0,%1,%2,%3}, {%4,%5,%6,%7}, {%8,%9}, {%0,%1,%2,%3};"
        : "+f"(c[0]), "+f"(c[1]), "+f"(c[2]), "+f"(c[3])
        : "r"(a[0]), "r"(a[1]), "r"(a[2]), "r"(a[3]), "r"(b[0]), "r"(b[1]));
}
__device__ __forceinline__ void split_bf16(float v, bf16& h, bf16& l) {
    h = __float2bfloat16(v);
    l = __float2bfloat16(v - __bfloat162float(h));
}

// ---------------------------------------------------------------------------
// Kernel 1: QKV projection (unchanged — measured at its fp32 FFMA floor).
// ---------------------------------------------------------------------------
__global__ void proj_kernel(const float* __restrict__ X,
                            const float* __restrict__ Wq, const float* __restrict__ bq,
                            const float* __restrict__ Wk, const float* __restrict__ bk,
                            const float* __restrict__ Wv, const float* __restrict__ bv)
{
    const int p  = blockIdx.y;
    const float* W    = (p == 0) ? Wq : (p == 1) ? Wk : Wv;
    const float* bias = (p == 0) ? bq : (p == 1) ? bk : bv;

    const int b  = blockIdx.z;
    const int i0 = blockIdx.x * 32;
    const int o  = threadIdx.x;

    __shared__ float Xs[CH][32];
    __shared__ float T[32][132];

    for (int idx = threadIdx.x; idx < CH * 32; idx += 128) {
        int c  = idx >> 5;
        int ii = idx & 31;
        Xs[c][ii] = X[((size_t)b * CH + c) * HW + i0 + ii];
    }
    __syncthreads();

    float acc[32];
#pragma unroll
    for (int ii = 0; ii < 32; ii++) acc[ii] = 0.f;
    for (int c = 0; c < CH; c += 4) {
        float4 w4 = *reinterpret_cast<const float4*>(&W[o * CH + c]);
        float w[4] = {w4.x, w4.y, w4.z, w4.w};
#pragma unroll
        for (int cc = 0; cc < 4; cc++)
#pragma unroll
            for (int ii = 0; ii < 32; ii++)
                acc[ii] += w[cc] * Xs[c + cc][ii];
    }
    const float bo = bias[o];

    if (p == 2) {
        float* op = &g_V[((size_t)b * CH + o) * HW + i0];
#pragma unroll
        for (int ii = 0; ii < 32; ii++) op[ii] = acc[ii] + bo;
    } else {
#pragma unroll
        for (int ii = 0; ii < 32; ii++) T[ii][o] = acc[ii] + bo;
        __syncthreads();
        bf16* hi = (p == 0) ? g_Qhi : g_Khi;
        bf16* lo = (p == 0) ? g_Qlo : g_Klo;
#pragma unroll
        for (int k = 0; k < 16; k++) {
            int gi  = threadIdx.x + k * 128;
            int row = gi >> 6;
            int cp  = (gi & 63) * 2;
            float v0 = T[row][cp];
            float v1 = T[row][cp + 1];
            bf16 h0, l0, h1, l1;
            split_bf16(v0, h0, l0);
            split_bf16(v1, h1, l1);
            size_t base = ((size_t)b * HW + i0 + row) * CH + cp;
            *reinterpret_cast<__nv_bfloat162*>(&hi[base]) = __nv_bfloat162(h0, h1);
            *reinterpret_cast<__nv_bfloat162*>(&lo[base]) = __nv_bfloat162(l0, l1);
        }
    }
}

// ---------------------------------------------------------------------------
// Kernel 2: scores — EXACT R10 config (measured best ~253us).
// CTA 128(i) x 128(j).  warps 2(wm: 64 rows) x 4(wn: 32 cols).
// k in 4 chunks of 32.  2-stage, one sync/chunk, pass-major.  2 CTAs/SM.
// ---------------------------------------------------------------------------
#define SC_TROW  80
#define SC_TILE  10240    // 128*80
#define SC_STAGE 40960    // 4 tiles
#define SC_SMEM  81920    // 2 stages

__global__ void __launch_bounds__(256, 2) scores_kernel()
{
    extern __shared__ char smem[];
    const uint32_t sb = smem_u32(smem);
    const int tid = threadIdx.x, wid = tid >> 5, lane = tid & 31;
    const int g = lane >> 2, t = lane & 3;
    const int wm = wid & 1, wn = wid >> 1;
    const int b = blockIdx.z, i0 = blockIdx.y * 128, j0 = blockIdx.x * 128;

    const bf16* bases[4] = {
        g_Qhi + ((size_t)b * HW + i0) * CH,
        g_Qlo + ((size_t)b * HW + i0) * CH,
        g_Khi + ((size_t)b * HW + j0) * CH,
        g_Klo + ((size_t)b * HW + j0) * CH };

    float acc[4][4][4];
#pragma unroll
    for (int a = 0; a < 4; a++)
#pragma unroll
        for (int n = 0; n < 4; n++)
#pragma unroll
            for (int r = 0; r < 4; r++) acc[a][n][r] = 0.f;

    // 4 tiles x 128 rows x 4 segs of 16B = 2048 ops = 8/thread
    auto issue = [&](int st, int kc) {
        uint32_t sd = sb + st * SC_STAGE;
#pragma unroll
        for (int w = 0; w < 8; w++) {
            int idx  = w * 256 + tid;
            int tile = idx >> 9;
            int row  = (idx >> 2) & 127;
            int seg  = idx & 3;
            cp16(sd + tile * SC_TILE + row * SC_TROW + seg * 16,
                 bases[tile] + (size_t)row * CH + kc * 32 + seg * 8);
        }
    };

    issue(0, 0); cp_commit();
    for (int kc = 0; kc < 4; kc++) {
        cp_wait<0>();
        __syncthreads();
        if (kc < 3) { issue((kc + 1) & 1, kc + 1); cp_commit(); }

        const uint32_t SB  = sb + (kc & 1) * SC_STAGE;
        const uint32_t TAh = SB, TAl = SB + SC_TILE;
        const uint32_t TBh = SB + 2 * SC_TILE, TBl = SB + 3 * SC_TILE;
        const uint32_t rowA = (wm * 64 + g) * SC_TROW;
        const uint32_t rowB = (wn * 32 + g) * SC_TROW;
#pragma unroll
        for (int ks = 0; ks < 2; ks++) {
            const uint32_t wo0 = ks * 32 + t * 4, wo1 = wo0 + 16;
            uint32_t ah[4][4], al[4][4], bh[4][2], bl[4][2];
#pragma unroll
            for (int mt = 0; mt < 4; mt++) {
                uint32_t o = rowA + mt * (16 * SC_TROW);
                ah[mt][0] = lds32(TAh + o + wo0);
                ah[mt][1] = lds32(TAh + o + 8 * SC_TROW + wo0);
                ah[mt][2] = lds32(TAh + o + wo1);
                ah[mt][3] = lds32(TAh + o + 8 * SC_TROW + wo1);
                al[mt][0] = lds32(TAl + o + wo0);
                al[mt][1] = lds32(TAl + o + 8 * SC_TROW + wo0);
                al[mt][2] = lds32(TAl + o + wo1);
                al[mt][3] = lds32(TAl + o + 8 * SC_TROW + wo1);
            }
#pragma unroll
            for (int nt = 0; nt < 4; nt++) {
                uint32_t o = rowB + nt * (8 * SC_TROW);
                bh[nt][0] = lds32(TBh + o + wo0);
                bh[nt][1] = lds32(TBh + o + wo1);
                bl[nt][0] = lds32(TBl + o + wo0);
                bl[nt][1] = lds32(TBl + o + wo1);
            }
            // pass-major: per-acc order stays hh -> hl -> lh
#pragma unroll
            for (int mt = 0; mt < 4; mt++)
#pragma unroll
                for (int nt = 0; nt < 4; nt++)
                    mma_bf16(acc[mt][nt], ah[mt], bh[nt]);
#pragma unroll
            for (int mt = 0; mt < 4; mt++)
#pragma unroll
                for (int nt = 0; nt < 4; nt++)
                    mma_bf16(acc[mt][nt], ah[mt], bl[nt]);
#pragma unroll
            for (int mt = 0; mt < 4; mt++)
#pragma unroll
                for (int nt = 0; nt < 4; nt++)
                    mma_bf16(acc[mt][nt], al[mt], bh[nt]);
        }
    }
    __syncthreads();   // before reusing stage smem for reduction

    // epilogue: exp, bf16 store (csum over the ROUNDED values), column partials
    float csum[4][2] = {};
    const size_t Eb = (size_t)b * HW * HW;
#pragma unroll
    for (int mt = 0; mt < 4; mt++) {
        const int r0 = i0 + wm * 64 + mt * 16 + g;
#pragma unroll
        for (int nt = 0; nt < 4; nt++) {
            const int jj = j0 + wn * 32 + nt * 8 + 2 * t;
            bf16 h0 = __float2bfloat16(__expf(acc[mt][nt][0]));
            bf16 h1 = __float2bfloat16(__expf(acc[mt][nt][1]));
            bf16 h2 = __float2bfloat16(__expf(acc[mt][nt][2]));
            bf16 h3 = __float2bfloat16(__expf(acc[mt][nt][3]));
            csum[nt][0] += __bfloat162float(h0) + __bfloat162float(h2);
            csum[nt][1] += __bfloat162float(h1) + __bfloat162float(h3);
            size_t o1 = Eb + (size_t)r0 * HW + jj;
            size_t o2 = o1 + (size_t)8 * HW;
            *reinterpret_cast<__nv_bfloat162*>(&g_E[o1]) = __nv_bfloat162(h0, h1);
            *reinterpret_cast<__nv_bfloat162*>(&g_E[o2]) = __nv_bfloat162(h2, h3);
        }
    }
#pragma unroll
    for (int nt = 0; nt < 4; nt++)
#pragma unroll
        for (int p = 0; p < 2; p++) {
            float v = csum[nt][p];
            v += __shfl_xor_sync(0xffffffffu, v, 4);
            v += __shfl_xor_sync(0xffffffffu, v, 8);
            v += __shfl_xor_sync(0xffffffffu, v, 16);
            csum[nt][p] = v;
        }
    float* red = reinterpret_cast<float*>(smem);
    if (lane < 4) {
#pragma unroll
        for (int nt = 0; nt < 4; nt++)
#pragma unroll
            for (int p = 0; p < 2; p++)
                red[wm * 128 + wn * 32 + nt * 8 + 2 * lane + p] = csum[nt][p];
    }
    __syncthreads();
    if (tid < 128)
        g_colpart[((b * RB) + blockIdx.y) * HW + j0 + tid] = red[tid] + red[128 + tid];
}

// ---------------------------------------------------------------------------
// Kernel 3: fused colsum + V normalize (single bf16).
// ---------------------------------------------------------------------------
__global__ void norm_kernel()
{
    int tid = blockIdx.x * blockDim.x + threadIdx.x;   // 0 .. BATCH*HW-1
    int b = tid >> 12;
    int j = tid & (HW - 1);
    float s = 0.f;
#pragma unroll 8
    for (int rb = 0; rb < RB; rb++)
        s += g_colpart[((b * RB) + rb) * HW + j];
    const float inv = 1.0f / s;
    const size_t base = (size_t)b * CH * HW + j;
#pragma unroll 4
    for (int c = 0; c < CH; c++)
        g_Vp[base + (size_t)c * HW] = __float2bfloat16(g_V[base + (size_t)c * HW] * inv);
}

// ---------------------------------------------------------------------------
// Kernel 4: AV — EXACT R12 config (measured best 115us).
// CTA m=c 128 x n=i 32 -> grid 512.  warps 4(wm) x 2(wn).  k in 64 chunks of 64.
// 2-stage, 4 CTAs/SM.
// ---------------------------------------------------------------------------
#define AV_TROW  144
#define AV_VT    18432    // 128*144
#define AV_STAGE 23040    // V(128) + E(32) rows
#define AV_SMEM  46080    // 2 stages

__global__ void __launch_bounds__(256, 4) av_kernel(const float* __restrict__ X,
                                                    float* __restrict__ out)
{
    extern __shared__ char smem[];
    const uint32_t sb = smem_u32(smem);
    const int tid = threadIdx.x, wid = tid >> 5, lane = tid & 31;
    const int g = lane >> 2, t = lane & 3;
    const int wm = wid & 3, wn = wid >> 2;
    const int b = blockIdx.y, i0 = blockIdx.x * 32;

    const bf16* Vp = g_Vp + (size_t)b * CH * HW;
    const bf16* Eb = g_E  + (size_t)b * HW * HW + (size_t)i0 * HW;

    float acc[2][2][4];
#pragma unroll
    for (int a = 0; a < 2; a++)
#pragma unroll
        for (int n = 0; n < 2; n++)
#pragma unroll
            for (int r = 0; r < 4; r++) acc[a][n][r] = 0.f;

    auto issue = [&](int st, int kc) {
        uint32_t sd = sb + st * AV_STAGE;
#pragma unroll
        for (int w = 0; w < 5; w++) {
            int idx = w * 256 + tid;           // 0..1279
            int r   = idx >> 3;
            int seg = idx & 7;
            if (r < 128) {
                cp16(sd + r * AV_TROW + seg * 16,
                     Vp + (size_t)r * HW + kc * 64 + seg * 8);
            } else {
                int row = r - 128;
                cp16(sd + AV_VT + row * AV_TROW + seg * 16,
                     Eb + (size_t)row * HW + kc * 64 + seg * 8);
            }
        }
    };

    issue(0, 0); cp_commit();
    for (int kc = 0; kc < 64; kc++) {
        if (kc < 63) { issue((kc + 1) & 1, kc + 1); cp_commit(); cp_wait<1>(); }
        else         { cp_wait<0>(); }
        __syncthreads();

        const uint32_t TA = sb + (kc & 1) * AV_STAGE;
        const uint32_t TB = TA + AV_VT;
        const uint32_t rowA = (wm * 32 + g) * AV_TROW;
        const uint32_t rowB = (wn * 16 + g) * AV_TROW;
#pragma unroll
        for (int ks = 0; ks < 4; ks++) {
            const uint32_t wo0 = ks * 32 + t * 4, wo1 = wo0 + 16;
            uint32_t ah[2][4], bh[2][2];
#pragma unroll
            for (int mt = 0; mt < 2; mt++) {
                uint32_t o = rowA + mt * (16 * AV_TROW);
                ah[mt][0] = lds32(TA + o + wo0);
                ah[mt][1] = lds32(TA + o + 8 * AV_TROW + wo0);
                ah[mt][2] = lds32(TA + o + wo1);
                ah[mt][3] = lds32(TA + o + 8 * AV_TROW + wo1);
            }
#pragma unroll
            for (int nt = 0; nt < 2; nt++) {
                uint32_t o = rowB + nt * (8 * AV_TROW);
                bh[nt][0] = lds32(TB + o + wo0);
                bh[nt][1] = lds32(TB + o + wo1);
            }
#pragma unroll
            for (int mt = 0; mt < 2; mt++)
#pragma unroll
                for (int nt = 0; nt < 2; nt++)
                    mma_bf16(acc[mt][nt], ah[mt], bh[nt]);
        }
        __syncthreads();
    }

    // epilogue: residual add + coalesced float2 stores
#pragma unroll
    for (int mt = 0; mt < 2; mt++) {
        const int cr = wm * 32 + mt * 16 + g;
#pragma unroll
        for (int nt = 0; nt < 2; nt++) {
            const int ii = i0 + wn * 16 + nt * 8 + 2 * t;
            size_t o1 = ((size_t)b * CH + cr) * HW + ii;
            size_t o2 = o1 + (size_t)8 * HW;   // channel +8
            float2 x1 = *reinterpret_cast<const float2*>(&X[o1]);
            float2 x2 = *reinterpret_cast<const float2*>(&X[o2]);
            float2 r1 = make_float2(x1.x + acc[mt][nt][0], x1.y + acc[mt][nt][1]);
            float2 r2 = make_float2(x2.x + acc[mt][nt][2], x2.y + acc[mt][nt][3]);
            *reinterpret_cast<float2*>(&out[o1]) = r1;
            *reinterpret_cast<float2*>(&out[o2]) = r2;
        }
    }
}

// ---------------------------------------------------------------------------
extern "C" void kernel_launch(void* const* d_in, const int* in_sizes, int n_in,
                              void* d_out, int out_size)
{
    const float* X  = (const float*)d_in[0];
    const float* Wq = (const float*)d_in[1];
    const float* bq = (const float*)d_in[2];
    const float* Wk = (const float*)d_in[3];
    const float* bk = (const float*)d_in[4];
    const float* Wv = (const float*)d_in[5];
    const float* bv = (const float*)d_in[6];
    float* out = (float*)d_out;

    cudaFuncSetAttribute(scores_kernel, cudaFuncAttributeMaxDynamicSharedMemorySize, SC_SMEM);
    cudaFuncSetAttribute(av_kernel,     cudaFuncAttributeMaxDynamicSharedMemorySize, AV_SMEM);

    proj_kernel<<<dim3(HW / 32, 3, BATCH), 128>>>(X, Wq, bq, Wk, bk, Wv, bv);
    scores_kernel<<<dim3(HW / 128, HW / 128, BATCH), 256, SC_SMEM>>>();
    norm_kernel<<<(BATCH * HW) / 256, 256>>>();
    av_kernel<<<dim3(HW / 32, BATCH), 256, AV_SMEM>>>(X, out);
}